// round 2
// baseline (speedup 1.0000x reference)
#include <cuda_runtime.h>
#include <math.h>

// Problem constants
#define KSTEPS 512
#define BATCH  64
#define NSTATE 128
#define NINPUT 32
#define HIDDEN 256
#define FIN    161      // 1 + NSTATE + NINPUT
#define FINPAD 164      // padded to multiple of 4 for float4 loads

// SMEM layout (in floats)
#define OFF_W2T   0        // [256][128] : w2t[j*128+i] = W2[i][j]
#define OFF_Z     32768    // 164 floats: z[0]=t, z[1..128]=y, z[129..160]=u, z[161..163]=0
#define OFF_HS    32932    // 256
#define OFF_KPART 33188    // 256 (two halves of layer-2 partial sums)
#define OFF_YSH   33444    // 128 (current base y)
#define OFF_U0    33572    // 32
#define OFF_U1    33604    // 32
#define OFF_D0    33636    // 32
#define OFF_D1    33668    // 32
#define SMEM_FLOATS 33700
#define SMEM_BYTES  (SMEM_FLOATS * 4)

__global__ __launch_bounds__(256, 1)
void ode_tsit5_kernel(const float* __restrict__ ts,
                      const float* __restrict__ y0,
                      const float* __restrict__ us,
                      const float* __restrict__ W1,
                      const float* __restrict__ b1,
                      const float* __restrict__ W2,
                      const float* __restrict__ b2,
                      float* __restrict__ out)
{
    // Tsit5 tableau (fp32)
    const float TH[6] = {0.0f, 0.161f, 0.327f, 0.9f, 0.9800255409045097f, 1.0f};
    const float A[5][5] = {
        {0.161f, 0.f, 0.f, 0.f, 0.f},
        {-0.008480655492356989f, 0.335480655492357f, 0.f, 0.f, 0.f},
        {2.8971530571054935f, -6.359448489975075f, 4.3622954328695815f, 0.f, 0.f},
        {5.325864828439257f, -11.748883564062828f, 7.4955393428898365f, -0.09249506636175525f, 0.f},
        {5.86145544294642f, -12.92096931784711f, 8.159367898576159f, -0.071584973281401f, -0.028269050394068383f}
    };
    const float Bw[6] = {0.09646076681806523f, 0.01f, 0.4798896504144996f,
                         1.379008574103742f, -3.290069515436081f, 2.324710524099774f};

    extern __shared__ float sm[];
    float* w2t   = sm + OFF_W2T;
    float* z     = sm + OFF_Z;
    float* hs    = sm + OFF_HS;
    float* kpart = sm + OFF_KPART;
    float* ysh   = sm + OFF_YSH;
    float* u0s   = sm + OFF_U0;
    float* u1s   = sm + OFF_U1;
    float* d0s   = sm + OFF_D0;
    float* d1s   = sm + OFF_D1;

    const int b = blockIdx.x;
    const int t = threadIdx.x;

    // ---- load W1 row for this hidden unit into registers (loop-invariant) ----
    float w1r[FINPAD];
#pragma unroll
    for (int i = 0; i < FINPAD; i++)
        w1r[i] = (i < FIN) ? __ldg(&W1[t * FIN + i]) : 0.0f;
    const float b1r = __ldg(&b1[t]);
    const float b2r = (t < NSTATE) ? __ldg(&b2[t]) : 0.0f;

    // ---- load W2 transposed into SMEM: w2t[j*128 + i] = W2[i*256 + j] ----
    for (int idx = t; idx < NSTATE * HIDDEN; idx += 256) {
        int i = idx >> 8;         // 0..127
        int j = idx & 255;        // 0..255
        w2t[j * NSTATE + i] = W2[idx];
    }

    // ---- init state ----
    if (t < NSTATE) {
        float y = y0[b * NSTATE + t];
        ysh[t] = y;
        z[1 + t] = y;
        out[(size_t)b * KSTEPS * NSTATE + t] = y;   // row 0 = y0
    }
    if (t == 0) {
        z[0] = ts[0];
        z[161] = 0.0f; z[162] = 0.0f; z[163] = 0.0f;
    }

    float kreg[6];
    const int i_out = t & 127;    // output index for layer-2
    const int half  = t >> 7;     // which half of the 256-length dot

    for (int step = 0; step < KSTEPS - 1; ++step) {
        const float t0   = ts[step];
        const float hcur = ts[step + 1] - t0;

        // ---- step prologue: input-signal Hermite data (threads 0..31) ----
        if (t < NINPUT) {
            const float* urow = us + ((size_t)b * KSTEPS + step) * NINPUT + t;
            float u0v = urow[0];
            float u1v = urow[NINPUT];
            float d1v = (u1v - u0v) / hcur;
            float d0v = d1v;
            if (step > 0) {
                float um1 = urow[-NINPUT];
                float hprev = t0 - ts[step - 1];
                d0v = (u0v - um1) / hprev;
            }
            u0s[t] = u0v; u1s[t] = u1v; d0s[t] = d0v; d1s[t] = d1v;
            z[129 + t] = u0v;     // theta = 0 for stage 0
        }
        if (t == 0) z[0] = t0;

#pragma unroll
        for (int s = 0; s < 6; s++) {
            __syncthreads();
            // ---------- layer 1: hidden[t] = tanh(W1[t,:] . z + b1[t]) ----------
            {
                float ax = 0.f, ay = 0.f, az = 0.f, aw = 0.f;
                const float4* z4 = (const float4*)z;
#pragma unroll
                for (int q = 0; q < FINPAD / 4; q++) {
                    float4 zz = z4[q];
                    ax = fmaf(w1r[4 * q + 0], zz.x, ax);
                    ay = fmaf(w1r[4 * q + 1], zz.y, ay);
                    az = fmaf(w1r[4 * q + 2], zz.z, az);
                    aw = fmaf(w1r[4 * q + 3], zz.w, aw);
                }
                float act = (ax + ay) + (az + aw) + b1r;
                hs[t] = tanhf(act);
            }
            __syncthreads();
            // ---------- layer 2 partials: out[i] += W2[i, half*128 + j] * h[...] ----------
            {
                const float* w2p = w2t + (half * 128) * NSTATE + i_out;
                const float4* h4 = (const float4*)(hs + half * 128);
                float c0 = 0.f, c1 = 0.f, c2 = 0.f, c3 = 0.f;
#pragma unroll
                for (int q = 0; q < 32; q++) {
                    float4 hh = h4[q];
                    c0 = fmaf(w2p[(4 * q + 0) * NSTATE], hh.x, c0);
                    c1 = fmaf(w2p[(4 * q + 1) * NSTATE], hh.y, c1);
                    c2 = fmaf(w2p[(4 * q + 2) * NSTATE], hh.z, c2);
                    c3 = fmaf(w2p[(4 * q + 3) * NSTATE], hh.w, c3);
                }
                kpart[t] = (c0 + c1) + (c2 + c3);
            }
            __syncthreads();
            // ---------- epilogue ----------
            if (t < NSTATE) {
                float kv = kpart[t] + kpart[128 + t] + b2r;
                kreg[s] = kv;
                float yb = ysh[t];
                if (s < 5) {
                    float yt = yb;
#pragma unroll
                    for (int j = 0; j <= s; j++)
                        yt = fmaf(hcur * A[s][j], kreg[j], yt);
                    z[1 + t] = yt;
                } else {
                    float yn = yb;
#pragma unroll
                    for (int j = 0; j < 6; j++)
                        yn = fmaf(hcur * Bw[j], kreg[j], yn);
                    ysh[t] = yn;
                    z[1 + t] = yn;
                    out[((size_t)b * KSTEPS + step + 1) * NSTATE + t] = yn;
                }
            } else if (t < 160) {
                if (s < 5) {
                    // u(theta) for the next stage via cubic Hermite (compile-time theta)
                    int l = t - 128;
                    float th = TH[s + 1];
                    float t2 = th * th, t3 = t2 * th;
                    float h00 = 2.f * t3 - 3.f * t2 + 1.f;
                    float h10 = t3 - 2.f * t2 + th;
                    float h01 = -2.f * t3 + 3.f * t2;
                    float h11 = t3 - t2;
                    float uv = h00 * u0s[l] + h01 * u1s[l]
                             + hcur * (h10 * d0s[l] + h11 * d1s[l]);
                    z[129 + l] = uv;
                }
            } else if (t == 192) {
                if (s < 5) z[0] = fmaf(TH[s + 1], hcur, t0);
            }
        }
    }
}

extern "C" void kernel_launch(void* const* d_in, const int* in_sizes, int n_in,
                              void* d_out, int out_size)
{
    // Map inputs by element count (all sizes are distinct)
    const float *ts = nullptr, *y0 = nullptr, *us = nullptr;
    const float *W1 = nullptr, *b1 = nullptr, *W2 = nullptr, *b2 = nullptr;
    for (int i = 0; i < n_in; i++) {
        switch (in_sizes[i]) {
            case 512:      ts = (const float*)d_in[i]; break;   // KSTEPS
            case 8192:     y0 = (const float*)d_in[i]; break;   // 64*128
            case 1048576:  us = (const float*)d_in[i]; break;   // 64*512*32
            case 41216:    W1 = (const float*)d_in[i]; break;   // 256*161
            case 256:      b1 = (const float*)d_in[i]; break;
            case 32768:    W2 = (const float*)d_in[i]; break;   // 128*256
            case 128:      b2 = (const float*)d_in[i]; break;
            default: break;
        }
    }
    float* out = (float*)d_out;

    cudaFuncSetAttribute(ode_tsit5_kernel,
                         cudaFuncAttributeMaxDynamicSharedMemorySize, SMEM_BYTES);
    ode_tsit5_kernel<<<BATCH, 256, SMEM_BYTES>>>(ts, y0, us, W1, b1, W2, b2, out);
}

// round 4
// speedup vs baseline: 1.0209x; 1.0209x over previous
#include <cuda_runtime.h>
#include <math.h>

// Problem constants
#define KSTEPS 512
#define BATCH  64
#define NSTATE 128
#define NINPUT 32
#define HIDDEN 256
#define FIN    161      // 1 + NSTATE + NINPUT
#define HALF   84       // padded half fan-in (2*84 = 168 = 42 float4)

// SMEM layout (float offsets)
#define OFF_W2   0          // 32768 floats = 16384 packed u64 pairs: w2u[j2*128+i] = (W2[i][2j2], W2[i][2j2+1])
#define OFF_Z    32768      // 168 floats: z[0]=t, z[1..128]=y, z[129..160]=u, z[161..167]=0
#define OFF_HS   32936      // 256 (tanh outputs)           -- 16B aligned
#define OFF_HP   33192      // 512 (layer-1 half partials)
#define OFF_KP   33704      // 512 (layer-2 quarter partials)
#define OFF_TS   34216      // 512 (time grid)
#define SMEM_FLOATS 34728
#define SMEM_BYTES  (SMEM_FLOATS * 4)

__device__ __forceinline__ unsigned long long ffma2(unsigned long long a,
                                                    unsigned long long b,
                                                    unsigned long long c) {
    unsigned long long d;
    asm("fma.rn.f32x2 %0, %1, %2, %3;" : "=l"(d) : "l"(a), "l"(b), "l"(c));
    return d;
}
__device__ __forceinline__ float lo32(unsigned long long v) { return __uint_as_float((unsigned)v); }
__device__ __forceinline__ float hi32(unsigned long long v) { return __uint_as_float((unsigned)(v >> 32)); }
__device__ __forceinline__ unsigned long long pack2(float a, float b) {
    return (unsigned long long)__float_as_uint(a) | ((unsigned long long)__float_as_uint(b) << 32);
}

__global__ __launch_bounds__(512, 1)
void ode_tsit5_kernel(const float* __restrict__ ts,
                      const float* __restrict__ y0,
                      const float* __restrict__ us,
                      const float* __restrict__ W1,
                      const float* __restrict__ b1,
                      const float* __restrict__ W2,
                      const float* __restrict__ b2,
                      float* __restrict__ out)
{
    const float TH[6] = {0.0f, 0.161f, 0.327f, 0.9f, 0.9800255409045097f, 1.0f};
    const float A[5][5] = {
        {0.161f, 0.f, 0.f, 0.f, 0.f},
        {-0.008480655492356989f, 0.335480655492357f, 0.f, 0.f, 0.f},
        {2.8971530571054935f, -6.359448489975075f, 4.3622954328695815f, 0.f, 0.f},
        {5.325864828439257f, -11.748883564062828f, 7.4955393428898365f, -0.09249506636175525f, 0.f},
        {5.86145544294642f, -12.92096931784711f, 8.159367898576159f, -0.071584973281401f, -0.028269050394068383f}
    };
    const float Bw[6] = {0.09646076681806523f, 0.01f, 0.4798896504144996f,
                         1.379008574103742f, -3.290069515436081f, 2.324710524099774f};

    extern __shared__ float sm[];
    float* zbuf = sm + OFF_Z;
    float* hs   = sm + OFF_HS;
    float* hp   = sm + OFF_HP;
    float* kp   = sm + OFF_KP;
    float* tss  = sm + OFF_TS;
    unsigned long long* w2u = (unsigned long long*)(sm + OFF_W2);

    const int b = blockIdx.x;
    const int t = threadIdx.x;

    // roles
    const int hu = t & 255;          // layer-1 hidden unit
    const int p  = t >> 8;           // layer-1 half (warps 0-7: p=0, warps 8-15: p=1)
    const int i  = t & 127;          // layer-2 output index
    const int q  = (t >> 7) & 3;     // layer-2 quarter of the K=256 dot

    // ---- W1 half-row into registers as f32x2 pairs (42 u64 = 84 regs) ----
    unsigned long long w1r[42];
#pragma unroll
    for (int m = 0; m < 42; m++) {
        int j0 = p * HALF + 2 * m;
        int j1 = j0 + 1;
        float a  = (j0 < FIN) ? __ldg(&W1[hu * FIN + j0]) : 0.0f;
        float bb = (j1 < FIN) ? __ldg(&W1[hu * FIN + j1]) : 0.0f;
        w1r[m] = pack2(a, bb);
    }
    const float b1r = (t < 256) ? __ldg(&b1[t]) : 0.0f;
    const float b2r = (t < 128) ? __ldg(&b2[t]) : 0.0f;

    // ---- W2 packed pairs into smem: w2u[j2*128 + i] = (W2[i][2j2], W2[i][2j2+1]) ----
    {
        const float2* W2v = (const float2*)W2;   // [128][128] float2 per row
        for (int idx = t; idx < NSTATE * HIDDEN / 2; idx += 512) {
            int ii = idx >> 7;        // 0..127 output row
            int j2 = idx & 127;       // 0..127 pair index (coalesced global read)
            float2 w = W2v[ii * 128 + j2];
            w2u[j2 * 128 + ii] = pack2(w.x, w.y);
        }
    }
    // ---- time grid to smem ----
    if (t < KSTEPS) tss[t] = ts[t];

    // ---- init state ----
    float yreg = 0.0f;
    if (t < NSTATE) {
        yreg = y0[b * NSTATE + t];
        zbuf[1 + t] = yreg;
        out[(size_t)b * KSTEPS * NSTATE + t] = yreg;   // row 0 = y0
    }
    if (t >= 161 && t < 168) zbuf[t] = 0.0f;           // pad tail

    float kreg[6];
    float u0v = 0.f, u1v = 0.f, d0v = 0.f, d1v = 0.f;  // per-thread u state (threads 128-159)

    __syncthreads();

    for (int step = 0; step < KSTEPS - 1; ++step) {
        const float t0   = tss[step];
        const float hcur = tss[step + 1] - t0;

        // ---- step prologue: u Hermite data in registers (threads 128-159) ----
        if (t >= 128 && t < 160) {
            const int l = t - 128;
            const float* urow = us + ((size_t)b * KSTEPS + step) * NINPUT + l;
            u0v = urow[0];
            u1v = urow[NINPUT];
            d1v = (u1v - u0v) / hcur;
            d0v = d1v;
            if (step > 0) {
                float um1 = urow[-NINPUT];
                float hprev = t0 - tss[step - 1];
                d0v = (u0v - um1) / hprev;
            }
            zbuf[129 + l] = u0v;         // theta = 0 for stage 0
        }
        if (t == 160) zbuf[0] = t0;

#pragma unroll
        for (int s = 0; s < 6; s++) {
            __syncthreads();   // B0: z ready
            // ---------- layer 1 half-dot: hp[p][hu] = W1[hu, half] . z[half] ----------
            {
                const ulonglong2* zq = (const ulonglong2*)(zbuf + p * HALF);
                unsigned long long a0 = 0ull, a1 = 0ull;   // (0.f,0.f)
#pragma unroll
                for (int m = 0; m < 21; m++) {
                    ulonglong2 zz = zq[m];
                    a0 = ffma2(w1r[2 * m],     zz.x, a0);
                    a1 = ffma2(w1r[2 * m + 1], zz.y, a1);
                }
                hp[p * 256 + hu] = (lo32(a0) + hi32(a0)) + (lo32(a1) + hi32(a1));
            }
            __syncthreads();   // B1: partials ready
            // ---------- combine + tanh ----------
            if (t < 256) {
                float act = hp[t] + hp[256 + t] + b1r;
                hs[t] = tanhf(act);
            }
            __syncthreads();   // B2: hs ready
            // ---------- layer 2 quarter-dot: kp[q][i] = W2[i, quarter] . h[quarter] ----------
            {
                const ulonglong2* hq = (const ulonglong2*)(hs + q * 64);
                const unsigned long long* w2p = w2u + q * 32 * 128 + i;
                unsigned long long a0 = 0ull, a1 = 0ull;
#pragma unroll
                for (int m = 0; m < 16; m++) {
                    ulonglong2 hh = hq[m];
                    a0 = ffma2(w2p[(2 * m) * 128],     hh.x, a0);
                    a1 = ffma2(w2p[(2 * m + 1) * 128], hh.y, a1);
                }
                kp[q * 128 + i] = (lo32(a0) + hi32(a0)) + (lo32(a1) + hi32(a1));
            }
            __syncthreads();   // B3: k partials ready
            // ---------- epilogue ----------
            if (t < 128) {
                float kv = (kp[i] + kp[128 + i]) + (kp[256 + i] + kp[384 + i]) + b2r;
                kreg[s] = kv;
                if (s < 5) {
                    float yt = yreg;
#pragma unroll
                    for (int j = 0; j <= s; j++)
                        yt = fmaf(hcur * A[s][j], kreg[j], yt);
                    zbuf[1 + i] = yt;
                } else {
                    float yn = yreg;
#pragma unroll
                    for (int j = 0; j < 6; j++)
                        yn = fmaf(hcur * Bw[j], kreg[j], yn);
                    yreg = yn;
                    zbuf[1 + i] = yn;
                    out[((size_t)b * KSTEPS + step + 1) * NSTATE + i] = yn;
                }
            } else if (t < 160) {
                if (s < 5) {
                    const int l = t - 128;
                    float th = TH[s + 1];
                    float t2 = th * th, t3 = t2 * th;
                    float h00 = 2.f * t3 - 3.f * t2 + 1.f;
                    float h10 = t3 - 2.f * t2 + th;
                    float h01 = -2.f * t3 + 3.f * t2;
                    float h11 = t3 - t2;
                    zbuf[129 + l] = h00 * u0v + h01 * u1v
                                  + hcur * (h10 * d0v + h11 * d1v);
                }
            } else if (t == 160) {
                if (s < 5) zbuf[0] = fmaf(TH[s + 1], hcur, t0);
            }
        }
    }
}

extern "C" void kernel_launch(void* const* d_in, const int* in_sizes, int n_in,
                              void* d_out, int out_size)
{
    // Map inputs by element count (all sizes are distinct)
    const float *ts = nullptr, *y0 = nullptr, *us = nullptr;
    const float *W1 = nullptr, *b1 = nullptr, *W2 = nullptr, *b2 = nullptr;
    for (int i = 0; i < n_in; i++) {
        switch (in_sizes[i]) {
            case 512:      ts = (const float*)d_in[i]; break;   // KSTEPS
            case 8192:     y0 = (const float*)d_in[i]; break;   // 64*128
            case 1048576:  us = (const float*)d_in[i]; break;   // 64*512*32
            case 41216:    W1 = (const float*)d_in[i]; break;   // 256*161
            case 256:      b1 = (const float*)d_in[i]; break;
            case 32768:    W2 = (const float*)d_in[i]; break;   // 128*256
            case 128:      b2 = (const float*)d_in[i]; break;
            default: break;
        }
    }
    float* out = (float*)d_out;

    cudaFuncSetAttribute(ode_tsit5_kernel,
                         cudaFuncAttributeMaxDynamicSharedMemorySize, SMEM_BYTES);
    ode_tsit5_kernel<<<BATCH, 512, SMEM_BYTES>>>(ts, y0, us, W1, b1, W2, b2, out);
}

// round 5
// speedup vs baseline: 1.0637x; 1.0419x over previous
#include <cuda_runtime.h>
#include <math.h>

// Problem constants
#define KSTEPS 512
#define BATCH  64
#define NSTATE 128
#define NINPUT 32
#define HIDDEN 256
#define FIN    161      // 1 + NSTATE + NINPUT
#define HALF   84       // half fan-in, padded (2*84 = 168)

// SMEM layout (float offsets)
#define OFF_W2   0          // 32768 floats: w2q[j4*128+i] = float4(W2[i][4j4..4j4+3]) as ulonglong2
#define OFF_Z    32768      // 168 floats: z[0]=t, z[1..128]=y, z[129..160]=u, z[161..167]=0
#define OFF_HS   32936      // 256 (tanh outputs), 16B aligned
#define OFF_KP   33192      // 512 (layer-2 quarter partials)
#define OFF_TS   33704      // 512 (time grid)
#define SMEM_FLOATS 34216
#define SMEM_BYTES  (SMEM_FLOATS * 4)

__device__ __forceinline__ unsigned long long ffma2(unsigned long long a,
                                                    unsigned long long b,
                                                    unsigned long long c) {
    unsigned long long d;
    asm("fma.rn.f32x2 %0, %1, %2, %3;" : "=l"(d) : "l"(a), "l"(b), "l"(c));
    return d;
}
__device__ __forceinline__ float lo32(unsigned long long v) { return __uint_as_float((unsigned)v); }
__device__ __forceinline__ float hi32(unsigned long long v) { return __uint_as_float((unsigned)(v >> 32)); }
__device__ __forceinline__ unsigned long long pack2(float a, float b) {
    return (unsigned long long)__float_as_uint(a) | ((unsigned long long)__float_as_uint(b) << 32);
}
__device__ __forceinline__ float tanh_fast(float x) {
    float y;
    asm("tanh.approx.f32 %0, %1;" : "=f"(y) : "f"(x));
    return y;
}

__global__ __launch_bounds__(512, 1)
void ode_tsit5_kernel(const float* __restrict__ ts,
                      const float* __restrict__ y0,
                      const float* __restrict__ us,
                      const float* __restrict__ W1,
                      const float* __restrict__ b1,
                      const float* __restrict__ W2,
                      const float* __restrict__ b2,
                      float* __restrict__ out)
{
    const float TH[6] = {0.0f, 0.161f, 0.327f, 0.9f, 0.9800255409045097f, 1.0f};
    const float A[5][5] = {
        {0.161f, 0.f, 0.f, 0.f, 0.f},
        {-0.008480655492356989f, 0.335480655492357f, 0.f, 0.f, 0.f},
        {2.8971530571054935f, -6.359448489975075f, 4.3622954328695815f, 0.f, 0.f},
        {5.325864828439257f, -11.748883564062828f, 7.4955393428898365f, -0.09249506636175525f, 0.f},
        {5.86145544294642f, -12.92096931784711f, 8.159367898576159f, -0.071584973281401f, -0.028269050394068383f}
    };
    const float Bw[6] = {0.09646076681806523f, 0.01f, 0.4798896504144996f,
                         1.379008574103742f, -3.290069515436081f, 2.324710524099774f};

    extern __shared__ float sm[];
    float* zbuf = sm + OFF_Z;
    float* hs   = sm + OFF_HS;
    float* kp   = sm + OFF_KP;
    float* tss  = sm + OFF_TS;
    ulonglong2* w2q = (ulonglong2*)(sm + OFF_W2);   // [64][128] of 16B

    const int b = blockIdx.x;
    const int t = threadIdx.x;

    // roles
    const int hu = t >> 1;           // layer-1 hidden unit (pairs of threads)
    const int p  = t & 1;            // which half of the fan-in
    const int i  = t & 127;          // layer-2 output index
    const int q  = (t >> 7) & 3;     // layer-2 quarter of the K=256 dot

    // ---- W1 half-row into registers as f32x2 pairs (42 u64 = 84 regs) ----
    unsigned long long w1r[42];
#pragma unroll
    for (int m = 0; m < 42; m++) {
        int j0 = p * HALF + 2 * m;
        int j1 = j0 + 1;
        float a  = (j0 < FIN) ? __ldg(&W1[hu * FIN + j0]) : 0.0f;
        float bb = (j1 < FIN) ? __ldg(&W1[hu * FIN + j1]) : 0.0f;
        w1r[m] = pack2(a, bb);
    }
    const float b1r = __ldg(&b1[hu]);
    const float b2r = (t < 128) ? __ldg(&b2[t]) : 0.0f;

    // ---- W2 packed float4-in-j into smem: w2q[j4*128 + i] = W2[i][4j4..4j4+3] ----
    {
        const float4* W2v = (const float4*)W2;   // [128][64] float4 per row
        for (int idx = t; idx < NSTATE * HIDDEN / 4; idx += 512) {
            int ii = idx >> 6;        // 0..127 output row
            int j4 = idx & 63;        // 0..63 quad index (coalesced global read)
            float4 w = W2v[ii * 64 + j4];
            ulonglong2 pk;
            pk.x = pack2(w.x, w.y);
            pk.y = pack2(w.z, w.w);
            w2q[j4 * 128 + ii] = pk;
        }
    }
    // ---- time grid to smem ----
    if (t < KSTEPS) tss[t] = ts[t];

    // ---- init state ----
    float yreg = 0.0f;
    if (t < NSTATE) {
        yreg = y0[b * NSTATE + t];
        zbuf[1 + t] = yreg;
        out[(size_t)b * KSTEPS * NSTATE + t] = yreg;   // row 0 = y0
    }
    if (t >= 161 && t < 168) zbuf[t] = 0.0f;           // pad tail

    // ---- u-signal register state (threads 128-159) ----
    const bool ut = (t >= 128 && t < 160);
    const int  l  = t - 128;
    float u0v = 0.f, u1v = 0.f, d0v = 0.f, d1v = 0.f, unext = 0.f;
    const float* urow = us + (size_t)b * KSTEPS * NINPUT + l;
    if (ut) {
        u0v   = urow[0];
        unext = urow[NINPUT];          // us[step=1]
    }

    float kreg[6];
    __syncthreads();

    for (int step = 0; step < KSTEPS - 1; ++step) {
        const float t0   = tss[step];
        const float hcur = tss[step + 1] - t0;

        // ---- step prologue (register-chained u state; single new load per step) ----
        if (ut) {
            u1v = unext;
            float dn = (u1v - u0v) / hcur;
            if (step == 0) d0v = dn;   // else d0v carried from previous d1v
            d1v = dn;
            zbuf[129 + l] = u0v;       // theta = 0 for stage 0
            if (step + 2 < KSTEPS)     // prefetch next step's right endpoint
                unext = urow[(size_t)(step + 2) * NINPUT];
        }
        if (t == 160) zbuf[0] = t0;

#pragma unroll
        for (int s = 0; s < 6; s++) {
            __syncthreads();   // B0: z ready
            // ---------- layer 1: pairwise half-dot + shfl combine + tanh ----------
            {
                const ulonglong2* zq = (const ulonglong2*)(zbuf + p * HALF);
                unsigned long long a0 = 0ull, a1 = 0ull, a2 = 0ull, a3 = 0ull;
#pragma unroll
                for (int m = 0; m < 10; m++) {
                    ulonglong2 z0 = zq[2 * m];
                    ulonglong2 z1 = zq[2 * m + 1];
                    a0 = ffma2(w1r[4 * m],     z0.x, a0);
                    a1 = ffma2(w1r[4 * m + 1], z0.y, a1);
                    a2 = ffma2(w1r[4 * m + 2], z1.x, a2);
                    a3 = ffma2(w1r[4 * m + 3], z1.y, a3);
                }
                {   // tail m=20 (pairs 40,41)
                    ulonglong2 z0 = zq[20];
                    a0 = ffma2(w1r[40], z0.x, a0);
                    a1 = ffma2(w1r[41], z0.y, a1);
                }
                float half_dot = (lo32(a0) + hi32(a0)) + (lo32(a1) + hi32(a1))
                               + (lo32(a2) + hi32(a2)) + (lo32(a3) + hi32(a3));
                float other = __shfl_xor_sync(0xFFFFFFFFu, half_dot, 1);
                if (p == 0)
                    hs[hu] = tanh_fast(half_dot + other + b1r);
            }
            __syncthreads();   // B1: hs ready
            // ---------- layer 2 quarter-dot: kp[q][i] = W2[i, quarter] . h[quarter] ----------
            {
                const ulonglong2* hq = (const ulonglong2*)(hs + q * 64);
                const ulonglong2* wp = w2q + q * 16 * 128 + i;
                unsigned long long a0 = 0ull, a1 = 0ull, a2 = 0ull, a3 = 0ull;
#pragma unroll
                for (int m = 0; m < 8; m++) {
                    ulonglong2 w0 = wp[(2 * m) * 128];
                    ulonglong2 hh0 = hq[2 * m];
                    a0 = ffma2(w0.x, hh0.x, a0);
                    a1 = ffma2(w0.y, hh0.y, a1);
                    ulonglong2 w1 = wp[(2 * m + 1) * 128];
                    ulonglong2 hh1 = hq[2 * m + 1];
                    a2 = ffma2(w1.x, hh1.x, a2);
                    a3 = ffma2(w1.y, hh1.y, a3);
                }
                kp[q * 128 + i] = (lo32(a0) + hi32(a0)) + (lo32(a1) + hi32(a1))
                                + (lo32(a2) + hi32(a2)) + (lo32(a3) + hi32(a3));
            }
            __syncthreads();   // B2: kp ready
            // ---------- epilogue ----------
            if (t < 128) {
                float kv = (kp[i] + kp[128 + i]) + (kp[256 + i] + kp[384 + i]) + b2r;
                kreg[s] = kv;
                if (s < 5) {
                    float yt = yreg;
#pragma unroll
                    for (int j = 0; j <= s; j++)
                        yt = fmaf(hcur * A[s][j], kreg[j], yt);
                    zbuf[1 + i] = yt;
                } else {
                    float yn = yreg;
#pragma unroll
                    for (int j = 0; j < 6; j++)
                        yn = fmaf(hcur * Bw[j], kreg[j], yn);
                    yreg = yn;
                    zbuf[1 + i] = yn;
                    out[((size_t)b * KSTEPS + step + 1) * NSTATE + i] = yn;
                }
            } else if (ut) {
                if (s < 5) {
                    float th = TH[s + 1];
                    float t2 = th * th, t3 = t2 * th;
                    float h00 = 2.f * t3 - 3.f * t2 + 1.f;
                    float h10 = t3 - 2.f * t2 + th;
                    float h01 = -2.f * t3 + 3.f * t2;
                    float h11 = t3 - t2;
                    zbuf[129 + l] = h00 * u0v + h01 * u1v
                                  + hcur * (h10 * d0v + h11 * d1v);
                }
            } else if (t == 160) {
                if (s < 5) zbuf[0] = fmaf(TH[s + 1], hcur, t0);
            }
        }

        // carry u state to next step (u0 = this step's u1, d0 = this step's d1)
        if (ut) { u0v = u1v; d0v = d1v; }
    }
}

extern "C" void kernel_launch(void* const* d_in, const int* in_sizes, int n_in,
                              void* d_out, int out_size)
{
    // Map inputs by element count (all sizes are distinct)
    const float *ts = nullptr, *y0 = nullptr, *us = nullptr;
    const float *W1 = nullptr, *b1 = nullptr, *W2 = nullptr, *b2 = nullptr;
    for (int i = 0; i < n_in; i++) {
        switch (in_sizes[i]) {
            case 512:      ts = (const float*)d_in[i]; break;   // KSTEPS
            case 8192:     y0 = (const float*)d_in[i]; break;   // 64*128
            case 1048576:  us = (const float*)d_in[i]; break;   // 64*512*32
            case 41216:    W1 = (const float*)d_in[i]; break;   // 256*161
            case 256:      b1 = (const float*)d_in[i]; break;
            case 32768:    W2 = (const float*)d_in[i]; break;   // 128*256
            case 128:      b2 = (const float*)d_in[i]; break;
            default: break;
        }
    }
    float* out = (float*)d_out;

    cudaFuncSetAttribute(ode_tsit5_kernel,
                         cudaFuncAttributeMaxDynamicSharedMemorySize, SMEM_BYTES);
    ode_tsit5_kernel<<<BATCH, 512, SMEM_BYTES>>>(ts, y0, us, W1, b1, W2, b2, out);
}